// round 1
// baseline (speedup 1.0000x reference)
#include <cuda_runtime.h>

// SSD post-processing: decode + per-class greedy NMS.
//   loc_data  [8, 3000, 4]  f32
//   conf_data [8, 3000, 21] f32
//   priors    [3000, 4]     f32
//   out       [8, 21, 200, 5] f32  (score, x1, y1, x2, y2), zero-padded
//
// One CTA per (class, batch). Grid (21, 8). Class 0 CTAs only zero their slice.

#define NP    3000
#define NPAD  4096
#define NC    21
#define TOPK  200
#define NT    256

#define SMEM_BYTES (NPAD * 8 + NP * 4 * 5 + NP * 4)  // keys + 5 float arrays + keep

__global__ __launch_bounds__(NT, 2) void ssd_post_kernel(
    const float* __restrict__ loc,
    const float* __restrict__ conf,
    const float* __restrict__ priors,
    float* __restrict__ out)
{
    extern __shared__ unsigned char smem_raw[];
    unsigned long long* keys = (unsigned long long*)smem_raw;          // [4096]
    float* sx1   = (float*)(smem_raw + NPAD * 8);                      // [3000]
    float* sy1   = sx1 + NP;
    float* sx2   = sy1 + NP;
    float* sy2   = sx2 + NP;
    float* sarea = sy2 + NP;
    int*   skeep = (int*)(sarea + NP);                                 // [3000]
    __shared__ int s_i;
    __shared__ int s_nvalid;

    const int c   = blockIdx.x;
    const int b   = blockIdx.y;
    const int tid = threadIdx.x;

    float* outp = out + ((size_t)(b * NC + c)) * (TOPK * 5);
    // zero our output slice (harness poisons d_out)
    for (int k = tid; k < TOPK * 5; k += NT) outp[k] = 0.0f;
    if (c == 0) return;  // background class: zeros only

    const float NEG_INF = __int_as_float(0xff800000);

    // ---- build sort keys: (sortable(score) << 32) | ~idx  (stable desc) ----
    const float* confb = conf + (size_t)b * NP * NC + c;
    for (int p = tid; p < NPAD; p += NT) {
        unsigned long long key = 0ULL;
        if (p < NP) {
            float s = confb[(size_t)p * NC];
            if (!(s > 0.01f)) s = NEG_INF;  // invalid -> -inf, sorts last
            unsigned u = __float_as_uint(s);
            u = (u & 0x80000000u) ? ~u : (u | 0x80000000u);
            key = ((unsigned long long)u << 32) | (unsigned)(~p);
        }
        keys[p] = key;  // padding key 0 < any real key
    }
    if (tid == 0) s_nvalid = NP;
    __syncthreads();

    // ---- bitonic sort, descending, 4096 u64 keys ----
    for (int k = 2; k <= NPAD; k <<= 1) {
        for (int j = k >> 1; j > 0; j >>= 1) {
            for (int i = tid; i < NPAD; i += NT) {
                int ixj = i ^ j;
                if (ixj > i) {
                    unsigned long long a  = keys[i];
                    unsigned long long bb = keys[ixj];
                    bool sw = ((i & k) == 0) ? (a < bb) : (a > bb);
                    if (sw) { keys[i] = bb; keys[ixj] = a; }
                }
            }
            __syncthreads();
        }
    }

    // ---- gather in sorted order + decode boxes (exact reference op order) ----
    const float* locb = loc + (size_t)b * NP * 4;
    for (int r = tid; r < NP; r += NT) {
        unsigned long long key = keys[r];
        int idx = (int)(~(unsigned)key);
        unsigned uhi = (unsigned)(key >> 32);
        float s = (uhi & 0x80000000u) ? __uint_as_float(uhi & 0x7FFFFFFFu)
                                      : __uint_as_float(~uhi);
        int valid = (s > 0.01f) ? 1 : 0;
        skeep[r] = valid;
        if (!valid) atomicMin(&s_nvalid, r);  // invalid are a suffix after sort

        float4 l  = *(const float4*)(locb + (size_t)idx * 4);
        float4 pr = *(const float4*)(priors + (size_t)idx * 4);
        // cxcy = p_xy + (l_xy * 0.1) * p_wh ; wh = p_wh * exp(l_wh * 0.2)
        float cx = __fadd_rn(pr.x, __fmul_rn(__fmul_rn(l.x, 0.1f), pr.z));
        float cy = __fadd_rn(pr.y, __fmul_rn(__fmul_rn(l.y, 0.1f), pr.w));
        float w  = __fmul_rn(pr.z, expf(__fmul_rn(l.z, 0.2f)));
        float h  = __fmul_rn(pr.w, expf(__fmul_rn(l.w, 0.2f)));
        float x1 = __fsub_rn(cx, __fmul_rn(0.5f, w));
        float y1 = __fsub_rn(cy, __fmul_rn(0.5f, h));
        float x2 = __fadd_rn(x1, w);
        float y2 = __fadd_rn(y1, h);
        sx1[r] = x1; sy1[r] = y1; sx2[r] = x2; sy2[r] = y2;
        sarea[r] = __fmul_rn(__fsub_rn(x2, x1), __fsub_rn(y2, y1));
    }
    __syncthreads();
    const int nvalid = s_nvalid;

    // ---- greedy NMS: at most TOPK kept iterations matter for the output ----
    int cur = 0;
    int cnt = 0;  // replicated uniformly in every thread
    while (true) {
        __syncthreads();  // keep[] stable from previous suppression pass
        if (tid < 32) {
            // warp 0: find first kept index >= cur (sentinel at nvalid)
            int basep = cur;
            int found;
            while (true) {
                int p2 = basep + (int)tid;
                int kk = (p2 < nvalid) ? skeep[p2] : 1;
                unsigned m = __ballot_sync(0xffffffffu, kk != 0);
                if (m) { found = basep + __ffs(m) - 1; break; }
                basep += 32;
            }
            if (tid == 0) s_i = found;
        }
        __syncthreads();
        int i = s_i;
        if (i >= nvalid) break;

        if (tid == 0) {
            unsigned long long key = keys[i];
            unsigned uhi = (unsigned)(key >> 32);
            float s = (uhi & 0x80000000u) ? __uint_as_float(uhi & 0x7FFFFFFFu)
                                          : __uint_as_float(~uhi);
            float* o = outp + cnt * 5;
            o[0] = s; o[1] = sx1[i]; o[2] = sy1[i]; o[3] = sx2[i]; o[4] = sy2[i];
        }
        cnt++;
        if (cnt >= TOPK) break;  // later suppression can't affect the output

        // suppress j > i with IoU > 0.45 (reference's exact arithmetic)
        float bx1 = sx1[i], by1 = sy1[i], bx2 = sx2[i], by2 = sy2[i], ai = sarea[i];
        for (int j2 = i + 1 + tid; j2 < nvalid; j2 += NT) {
            if (skeep[j2]) {
                float ltx = fmaxf(bx1, sx1[j2]);
                float lty = fmaxf(by1, sy1[j2]);
                float rbx = fminf(bx2, sx2[j2]);
                float rby = fminf(by2, sy2[j2]);
                float wx = fmaxf(__fsub_rn(rbx, ltx), 0.0f);
                float wy = fmaxf(__fsub_rn(rby, lty), 0.0f);
                float inter = __fmul_rn(wx, wy);
                float uni = __fsub_rn(__fadd_rn(ai, sarea[j2]), inter);
                float iou = __fdiv_rn(inter, fmaxf(uni, 1e-12f));
                if (iou > 0.45f) skeep[j2] = 0;
            }
        }
        cur = i + 1;
    }
}

extern "C" void kernel_launch(void* const* d_in, const int* in_sizes, int n_in,
                              void* d_out, int out_size)
{
    // identify inputs by element count (robust to ordering)
    const float* loc = nullptr;
    const float* conf = nullptr;
    const float* priors = nullptr;
    for (int i = 0; i < n_in; i++) {
        if (in_sizes[i] == 8 * NP * 4)       loc    = (const float*)d_in[i];
        else if (in_sizes[i] == 8 * NP * NC) conf   = (const float*)d_in[i];
        else if (in_sizes[i] == NP * 4)      priors = (const float*)d_in[i];
    }
    float* out = (float*)d_out;

    static bool attr_set = false;
    // cudaFuncSetAttribute is host-side state, not a stream op: capture-safe.
    cudaFuncSetAttribute(ssd_post_kernel,
                         cudaFuncAttributeMaxDynamicSharedMemorySize, SMEM_BYTES);
    (void)attr_set;

    dim3 grid(NC, 8);
    ssd_post_kernel<<<grid, NT, SMEM_BYTES>>>(loc, conf, priors, out);
}

// round 2
// speedup vs baseline: 2.6251x; 2.6251x over previous
#include <cuda_runtime.h>

// SSD post-processing: decode + per-class greedy NMS.
//   loc_data  [8, 3000, 4]  f32
//   conf_data [8, 3000, 21] f32
//   priors    [3000, 4]     f32
//   out       [8, 21, 200, 5] f32  (score, x1, y1, x2, y2), zero-padded
//
// One CTA per (class, batch). Grid (21, 8). Class 0 CTAs only zero their slice.
// Phase 1: 256 threads bitonic-sort 4096 (score,idx) keys in smem.
// Phase 2: warp 0 alone runs candidate-driven greedy NMS:
//          kept[j] <=> IoU(j, every earlier kept) <= 0.45.
//          Accepted boxes live lane-distributed in registers; candidates are
//          decoded on the fly in batches of 32. No block barriers in phase 2.

#define NP    3000
#define NPAD  4096
#define NC    21
#define TOPK  200
#define NT    256
#define NSLOT 7   // ceil(TOPK/32) accepted boxes per lane

__global__ __launch_bounds__(NT, 2) void ssd_post_kernel(
    const float* __restrict__ loc,
    const float* __restrict__ conf,
    const float* __restrict__ priors,
    float* __restrict__ out)
{
    __shared__ unsigned long long keys[NPAD];

    const int c   = blockIdx.x;
    const int b   = blockIdx.y;
    const int tid = threadIdx.x;

    float* outp = out + ((size_t)(b * NC + c)) * (TOPK * 5);
    for (int k = tid; k < TOPK * 5; k += NT) outp[k] = 0.0f;
    if (c == 0) return;  // background class: zeros only

    const float NEG_INF = __int_as_float(0xff800000);

    // ---- build sort keys: (sortable(score) << 32) | ~idx  (stable desc) ----
    const float* confb = conf + (size_t)b * NP * NC + c;
    for (int p = tid; p < NPAD; p += NT) {
        unsigned long long key = 0ULL;
        if (p < NP) {
            float s = confb[(size_t)p * NC];
            if (!(s > 0.01f)) s = NEG_INF;  // invalid -> -inf, sorts last
            unsigned u = __float_as_uint(s);
            u = (u & 0x80000000u) ? ~u : (u | 0x80000000u);
            key = ((unsigned long long)u << 32) | (unsigned)(~p);
        }
        keys[p] = key;  // padding key 0 < any real key
    }
    __syncthreads();

    // ---- bitonic sort, descending, 4096 u64 keys ----
    for (int k = 2; k <= NPAD; k <<= 1) {
        for (int j = k >> 1; j > 0; j >>= 1) {
            for (int i = tid; i < NPAD; i += NT) {
                int ixj = i ^ j;
                if (ixj > i) {
                    unsigned long long a  = keys[i];
                    unsigned long long bb = keys[ixj];
                    bool sw = ((i & k) == 0) ? (a < bb) : (a > bb);
                    if (sw) { keys[i] = bb; keys[ixj] = a; }
                }
            }
            __syncthreads();
        }
    }

    // ---- phase 2: single-warp candidate-driven greedy NMS ----
    if (tid >= 32) return;
    const int lane = tid;
    const float* locb = loc + (size_t)b * NP * 4;

    // lane-distributed accepted list: accepted #a lives in lane (a&31), slot (a>>5)
    float ax1[NSLOT], ay1[NSLOT], ax2[NSLOT], ay2[NSLOT], aar[NSLOT];

    int  cnt  = 0;
    int  base = 0;
    bool done = false;

    while (!done) {
        // ---- load + decode a batch of 32 candidates (one per lane) ----
        int pos = base + lane;
        unsigned long long key = (pos < NPAD) ? keys[pos] : 0ULL;
        unsigned uhi = (unsigned)(key >> 32);
        float s = (uhi & 0x80000000u) ? __uint_as_float(uhi & 0x7FFFFFFFu)
                                      : __uint_as_float(~uhi);
        bool v = (s > 0.01f);  // validity is a prefix of the batch (sorted desc)

        float x1 = 0.f, y1 = 0.f, x2 = 0.f, y2 = 0.f, ar = 0.f;
        if (v) {
            int idx = (int)(~(unsigned)key);
            float4 l  = *(const float4*)(locb + (size_t)idx * 4);
            float4 pr = *(const float4*)(priors + (size_t)idx * 4);
            // exact reference op order (no FMA contraction)
            float cx = __fadd_rn(pr.x, __fmul_rn(__fmul_rn(l.x, 0.1f), pr.z));
            float cy = __fadd_rn(pr.y, __fmul_rn(__fmul_rn(l.y, 0.1f), pr.w));
            float w  = __fmul_rn(pr.z, expf(__fmul_rn(l.z, 0.2f)));
            float h  = __fmul_rn(pr.w, expf(__fmul_rn(l.w, 0.2f)));
            x1 = __fsub_rn(cx, __fmul_rn(0.5f, w));
            y1 = __fsub_rn(cy, __fmul_rn(0.5f, h));
            x2 = __fadd_rn(x1, w);
            y2 = __fadd_rn(y1, h);
            ar = __fmul_rn(__fsub_rn(x2, x1), __fsub_rn(y2, y1));
        }
        int nv = __popc(__ballot_sync(0xffffffffu, v));

        // ---- process the batch's candidates in score order ----
        for (int t = 0; t < nv; ++t) {
            float cs  = __shfl_sync(0xffffffffu, s,  t);
            float cx1 = __shfl_sync(0xffffffffu, x1, t);
            float cy1 = __shfl_sync(0xffffffffu, y1, t);
            float cx2 = __shfl_sync(0xffffffffu, x2, t);
            float cy2 = __shfl_sync(0xffffffffu, y2, t);
            float car = __shfl_sync(0xffffffffu, ar, t);

            // this lane holds slots 0..myslots-1 (accepted a with a&31==lane, a<cnt)
            int myslots = (cnt + 31 - lane) >> 5;
            bool ov = false;
            #pragma unroll
            for (int k = 0; k < NSLOT; ++k) {
                if (k < myslots) {
                    float ltx = fmaxf(cx1, ax1[k]);
                    float lty = fmaxf(cy1, ay1[k]);
                    float rbx = fminf(cx2, ax2[k]);
                    float rby = fminf(cy2, ay2[k]);
                    float wx = fmaxf(__fsub_rn(rbx, ltx), 0.0f);
                    float wy = fmaxf(__fsub_rn(rby, lty), 0.0f);
                    float inter = __fmul_rn(wx, wy);
                    float iou = 0.0f;
                    if (inter > 0.0f) {  // inter==0 -> reference iou==0 too
                        float uni = __fsub_rn(__fadd_rn(car, aar[k]), inter);
                        iou = __fdiv_rn(inter, fmaxf(uni, 1e-12f));
                    }
                    ov |= (iou > 0.45f);
                }
            }

            if (__ballot_sync(0xffffffffu, ov) == 0u) {
                // accept candidate t as kept #cnt
                int slot = cnt >> 5;
                int tgt  = cnt & 31;
                #pragma unroll
                for (int k = 0; k < NSLOT; ++k) {
                    if (k == slot && lane == tgt) {
                        ax1[k] = cx1; ay1[k] = cy1;
                        ax2[k] = cx2; ay2[k] = cy2; aar[k] = car;
                    }
                }
                if (lane == 0) {
                    float* o = outp + cnt * 5;
                    o[0] = cs; o[1] = cx1; o[2] = cy1; o[3] = cx2; o[4] = cy2;
                }
                cnt++;
                if (cnt >= TOPK) { done = true; break; }
            }
        }

        if (nv < 32) done = true;  // hit the invalid/padding suffix: no more candidates
        base += 32;
    }
}

extern "C" void kernel_launch(void* const* d_in, const int* in_sizes, int n_in,
                              void* d_out, int out_size)
{
    const float* loc = nullptr;
    const float* conf = nullptr;
    const float* priors = nullptr;
    for (int i = 0; i < n_in; i++) {
        if (in_sizes[i] == 8 * NP * 4)       loc    = (const float*)d_in[i];
        else if (in_sizes[i] == 8 * NP * NC) conf   = (const float*)d_in[i];
        else if (in_sizes[i] == NP * 4)      priors = (const float*)d_in[i];
    }
    float* out = (float*)d_out;

    dim3 grid(NC, 8);
    ssd_post_kernel<<<grid, NT>>>(loc, conf, priors, out);
}

// round 3
// speedup vs baseline: 3.4790x; 1.3253x over previous
#include <cuda_runtime.h>

// SSD post-processing: decode + per-class greedy NMS.
//   loc_data  [8, 3000, 4]  f32
//   conf_data [8, 3000, 21] f32
//   priors    [3000, 4]     f32
//   out       [8, 21, 200, 5] f32  (score, x1, y1, x2, y2), zero-padded
//
// One CTA per (class, batch), grid (21, 8).
// Phase 0: 256 threads bitonic-sort 4096 (score,idx) keys in smem, decode
//          boxes into sorted-order smem arrays.
// NMS: tiles of 256 candidates (1/thread).
//   Phase A: each thread tests its candidate vs the accepted list (parallel).
//   Phase B: serial in-tile resolution; 2 barriers per acceptance.
// Valid because suppressed boxes never suppress others:
//   kept(j) <=> IoU(j, every earlier kept) <= 0.45.

#define NP    3000
#define NPAD  4096
#define NC    21
#define TOPK  200
#define NT    256
#define TILE  256

// dynamic smem layout
#define OFF_KEYS   0
#define OFF_SX1    (NPAD * 8)
#define OFF_SY1    (OFF_SX1 + NP * 4)
#define OFF_SX2    (OFF_SY1 + NP * 4)
#define OFF_SY2    (OFF_SX2 + NP * 4)
#define OFF_SAREA  (OFF_SY2 + NP * 4)
#define OFF_ALIVE  (OFF_SAREA + NP * 4)
#define OFF_AX1    (OFF_ALIVE + 3072)
#define OFF_AY1    (OFF_AX1 + TOPK * 4)
#define OFF_AX2    (OFF_AY1 + TOPK * 4)
#define OFF_AY2    (OFF_AX2 + TOPK * 4)
#define OFF_AAR    (OFF_AY2 + TOPK * 4)
#define SMEM_BYTES (OFF_AAR + TOPK * 4)

// reference-exact IoU (no FMA contraction)
__device__ __forceinline__ float iou_rn(float ax1, float ay1, float ax2, float ay2, float aa,
                                        float bx1, float by1, float bx2, float by2, float ba)
{
    float ltx = fmaxf(ax1, bx1);
    float lty = fmaxf(ay1, by1);
    float rbx = fminf(ax2, bx2);
    float rby = fminf(ay2, by2);
    float wx  = fmaxf(__fsub_rn(rbx, ltx), 0.0f);
    float wy  = fmaxf(__fsub_rn(rby, lty), 0.0f);
    float inter = __fmul_rn(wx, wy);
    float uni   = __fsub_rn(__fadd_rn(aa, ba), inter);
    return __fdiv_rn(inter, fmaxf(uni, 1e-12f));
}

__global__ __launch_bounds__(NT, 2) void ssd_post_kernel(
    const float* __restrict__ loc,
    const float* __restrict__ conf,
    const float* __restrict__ priors,
    float* __restrict__ out)
{
    extern __shared__ unsigned char smem_raw[];
    unsigned long long* keys = (unsigned long long*)(smem_raw + OFF_KEYS);
    float* sx1   = (float*)(smem_raw + OFF_SX1);
    float* sy1   = (float*)(smem_raw + OFF_SY1);
    float* sx2   = (float*)(smem_raw + OFF_SX2);
    float* sy2   = (float*)(smem_raw + OFF_SY2);
    float* sarea = (float*)(smem_raw + OFF_SAREA);
    unsigned char* alive = (unsigned char*)(smem_raw + OFF_ALIVE);
    float* ax1 = (float*)(smem_raw + OFF_AX1);
    float* ay1 = (float*)(smem_raw + OFF_AY1);
    float* ax2 = (float*)(smem_raw + OFF_AX2);
    float* ay2 = (float*)(smem_raw + OFF_AY2);
    float* aar = (float*)(smem_raw + OFF_AAR);
    __shared__ int s_i;
    __shared__ int s_nvalid;

    const int c   = blockIdx.x;
    const int b   = blockIdx.y;
    const int tid = threadIdx.x;

    float* outp = out + ((size_t)(b * NC + c)) * (TOPK * 5);
    for (int k = tid; k < TOPK * 5; k += NT) outp[k] = 0.0f;
    if (c == 0) return;  // background class: zeros only

    const float NEG_INF = __int_as_float(0xff800000);

    // ---- build sort keys: (sortable(score) << 32) | ~idx  (stable desc) ----
    const float* confb = conf + (size_t)b * NP * NC + c;
    for (int p = tid; p < NPAD; p += NT) {
        unsigned long long key = 0ULL;
        if (p < NP) {
            float s = confb[(size_t)p * NC];
            if (!(s > 0.01f)) s = NEG_INF;  // invalid -> -inf, sorts last
            unsigned u = __float_as_uint(s);
            u = (u & 0x80000000u) ? ~u : (u | 0x80000000u);
            key = ((unsigned long long)u << 32) | (unsigned)(~p);
        }
        keys[p] = key;  // padding key 0 < any real key
    }
    if (tid == 0) s_nvalid = NP;
    __syncthreads();

    // ---- bitonic sort, descending, 4096 u64 keys ----
    for (int k = 2; k <= NPAD; k <<= 1) {
        for (int j = k >> 1; j > 0; j >>= 1) {
            #pragma unroll
            for (int w = 0; w < NPAD / NT; ++w) {
                int i = tid + w * NT;
                int ixj = i ^ j;
                if (ixj > i) {
                    unsigned long long a  = keys[i];
                    unsigned long long bb = keys[ixj];
                    bool sw = ((i & k) == 0) ? (a < bb) : (a > bb);
                    if (sw) { keys[i] = bb; keys[ixj] = a; }
                }
            }
            __syncthreads();
        }
    }

    // ---- gather in sorted order + decode boxes (exact reference op order) ----
    const float* locb = loc + (size_t)b * NP * 4;
    for (int r = tid; r < NP; r += NT) {
        unsigned long long key = keys[r];
        int idx = (int)(~(unsigned)key);
        unsigned uhi = (unsigned)(key >> 32);
        float s = (uhi & 0x80000000u) ? __uint_as_float(uhi & 0x7FFFFFFFu)
                                      : __uint_as_float(~uhi);
        int valid = (s > 0.01f) ? 1 : 0;
        alive[r] = (unsigned char)valid;
        if (!valid) atomicMin(&s_nvalid, r);  // invalid form a suffix after sort

        float4 l  = *(const float4*)(locb + (size_t)idx * 4);
        float4 pr = *(const float4*)(priors + (size_t)idx * 4);
        float cx = __fadd_rn(pr.x, __fmul_rn(__fmul_rn(l.x, 0.1f), pr.z));
        float cy = __fadd_rn(pr.y, __fmul_rn(__fmul_rn(l.y, 0.1f), pr.w));
        float w  = __fmul_rn(pr.z, expf(__fmul_rn(l.z, 0.2f)));
        float h  = __fmul_rn(pr.w, expf(__fmul_rn(l.w, 0.2f)));
        float x1 = __fsub_rn(cx, __fmul_rn(0.5f, w));
        float y1 = __fsub_rn(cy, __fmul_rn(0.5f, h));
        float x2 = __fadd_rn(x1, w);
        float y2 = __fadd_rn(y1, h);
        sx1[r] = x1; sy1[r] = y1; sx2[r] = x2; sy2[r] = y2;
        sarea[r] = __fmul_rn(__fsub_rn(x2, x1), __fsub_rn(y2, y1));
    }
    __syncthreads();
    const int nvalid = s_nvalid;

    // ---- tiled NMS ----
    int  cnt  = 0;      // uniform across threads
    bool done = false;

    for (int tb = 0; tb < nvalid && !done; tb += TILE) {
        const int  myIdx = tb + tid;
        const bool mine  = (myIdx < nvalid);
        bool myAlive = mine;

        float mx1 = 0.f, my1 = 0.f, mx2 = 0.f, my2 = 0.f, mar = 0.f, ms = 0.f;
        if (mine) {
            mx1 = sx1[myIdx]; my1 = sy1[myIdx];
            mx2 = sx2[myIdx]; my2 = sy2[myIdx];
            mar = sarea[myIdx];
            unsigned uhi = (unsigned)(keys[myIdx] >> 32);
            ms = (uhi & 0x80000000u) ? __uint_as_float(uhi & 0x7FFFFFFFu)
                                     : __uint_as_float(~uhi);
        }

        // Phase A: test my candidate vs accepted[0..cnt), early-out on overlap
        if (myAlive && cnt > 0) {
            bool ov = false;
            int j = 0;
            for (; j + 4 <= cnt; j += 4) {
                float i0 = iou_rn(mx1,my1,mx2,my2,mar, ax1[j+0],ay1[j+0],ax2[j+0],ay2[j+0],aar[j+0]);
                float i1 = iou_rn(mx1,my1,mx2,my2,mar, ax1[j+1],ay1[j+1],ax2[j+1],ay2[j+1],aar[j+1]);
                float i2 = iou_rn(mx1,my1,mx2,my2,mar, ax1[j+2],ay1[j+2],ax2[j+2],ay2[j+2],aar[j+2]);
                float i3 = iou_rn(mx1,my1,mx2,my2,mar, ax1[j+3],ay1[j+3],ax2[j+3],ay2[j+3],aar[j+3]);
                if ((i0 > 0.45f) | (i1 > 0.45f) | (i2 > 0.45f) | (i3 > 0.45f)) { ov = true; break; }
            }
            if (!ov) {
                for (; j < cnt; ++j) {
                    float ii = iou_rn(mx1,my1,mx2,my2,mar, ax1[j],ay1[j],ax2[j],ay2[j],aar[j]);
                    if (ii > 0.45f) { ov = true; break; }
                }
            }
            if (ov) { myAlive = false; alive[myIdx] = 0; }
        }
        __syncthreads();

        // Phase B: serial resolution within the tile
        const int tend = (tb + TILE < nvalid) ? (tb + TILE) : nvalid;
        int lcur = tb;
        while (true) {
            if (tid < 32) {
                int found = -1;
                for (int bp = lcur; bp < tend; bp += 32) {
                    int p = bp + tid;
                    int a = (p < tend) ? (int)alive[p] : 0;
                    unsigned m = __ballot_sync(0xffffffffu, a != 0);
                    if (m) { found = bp + __ffs(m) - 1; break; }
                }
                if (tid == 0) s_i = found;
            }
            __syncthreads();
            const int i = s_i;
            if (i < 0) break;  // tile exhausted

            if (myIdx == i) {
                // accept my candidate as kept #cnt
                alive[i] = 0;
                ax1[cnt] = mx1; ay1[cnt] = my1;
                ax2[cnt] = mx2; ay2[cnt] = my2; aar[cnt] = mar;
                float* o = outp + cnt * 5;
                o[0] = ms; o[1] = mx1; o[2] = my1; o[3] = mx2; o[4] = my2;
                myAlive = false;
            } else if (myAlive && myIdx > i) {
                // suppress vs the newly accepted box (stable candidate arrays)
                float ii = iou_rn(mx1,my1,mx2,my2,mar,
                                  sx1[i],sy1[i],sx2[i],sy2[i],sarea[i]);
                if (ii > 0.45f) { myAlive = false; alive[myIdx] = 0; }
            }
            cnt++;  // uniform
            if (cnt >= TOPK) done = true;
            __syncthreads();  // publish alive[] + accepted[] updates
            if (done) break;
            lcur = i + 1;
        }
    }
}

extern "C" void kernel_launch(void* const* d_in, const int* in_sizes, int n_in,
                              void* d_out, int out_size)
{
    const float* loc = nullptr;
    const float* conf = nullptr;
    const float* priors = nullptr;
    for (int i = 0; i < n_in; i++) {
        if (in_sizes[i] == 8 * NP * 4)       loc    = (const float*)d_in[i];
        else if (in_sizes[i] == 8 * NP * NC) conf   = (const float*)d_in[i];
        else if (in_sizes[i] == NP * 4)      priors = (const float*)d_in[i];
    }
    float* out = (float*)d_out;

    cudaFuncSetAttribute(ssd_post_kernel,
                         cudaFuncAttributeMaxDynamicSharedMemorySize, SMEM_BYTES);

    dim3 grid(NC, 8);
    ssd_post_kernel<<<grid, NT, SMEM_BYTES>>>(loc, conf, priors, out);
}